// round 17
// baseline (speedup 1.0000x reference)
#include <cuda_runtime.h>
#include <cuda_bf16.h>
#include <math.h>
#include <cstdint>

#define HW      16384
#define BATCH   4
#define MTOK    256
#define HD      256
#define INNER   128
#define DH      64

#define TWO_PI 6.2831853071795864769f

typedef unsigned long long u64;

// ---- cp.async helpers ------------------------------------------------------
__device__ __forceinline__ void cpa16(void* dst, const void* src) {
    unsigned d = (unsigned)__cvta_generic_to_shared(dst);
    asm volatile("cp.async.ca.shared.global [%0], [%1], 16;" :: "r"(d), "l"(src));
}
#define CPA_COMMIT() asm volatile("cp.async.commit_group;" ::: "memory")
#define CPA_WAIT0()  asm volatile("cp.async.wait_group 0;"  ::: "memory")
#define CPA_WAIT1()  asm volatile("cp.async.wait_group 1;"  ::: "memory")

// ---- mma.sync / ldmatrix helpers (baseline PTX, sm_80+) --------------------
__device__ __forceinline__ uint32_t smem_to_u32(const void* p) {
    uint32_t a;
    asm("{ .reg .u64 t; cvta.to.shared.u64 t, %1; cvt.u32.u64 %0, t; }" : "=r"(a) : "l"(p));
    return a;
}
__device__ __forceinline__ void ldsm4(uint32_t* r, uint32_t addr) {
    asm volatile("ldmatrix.sync.aligned.m8n8.x4.shared.b16 {%0,%1,%2,%3}, [%4];"
        : "=r"(r[0]), "=r"(r[1]), "=r"(r[2]), "=r"(r[3]) : "r"(addr));
}
__device__ __forceinline__ void ldsm2(uint32_t* r, uint32_t addr) {
    asm volatile("ldmatrix.sync.aligned.m8n8.x2.shared.b16 {%0,%1}, [%2];"
        : "=r"(r[0]), "=r"(r[1]) : "r"(addr));
}
__device__ __forceinline__ void mma16816(float* d, const uint32_t* a, const uint32_t* b) {
    asm volatile("mma.sync.aligned.m16n8k16.row.col.f32.bf16.bf16.f32 "
        "{%0,%1,%2,%3}, {%4,%5,%6,%7}, {%8,%9}, {%0,%1,%2,%3};"
        : "+f"(d[0]), "+f"(d[1]), "+f"(d[2]), "+f"(d[3])
        : "r"(a[0]), "r"(a[1]), "r"(a[2]), "r"(a[3]), "r"(b[0]), "r"(b[1]));
}

__device__ __forceinline__ int swz(int b) { return b ^ ((b >> 3) & 0x70); }

__device__ __forceinline__ void split2(float v0, float v1, uint32_t& hi, uint32_t& lo) {
    __nv_bfloat16 h0 = __float2bfloat16(v0), h1 = __float2bfloat16(v1);
    float r0 = v0 - __bfloat162float(h0);
    float r1 = v1 - __bfloat162float(h1);
    __nv_bfloat16 l0 = __float2bfloat16(r0), l1 = __float2bfloat16(r1);
    hi = ((uint32_t)__bfloat16_as_ushort(h1) << 16) | __bfloat16_as_ushort(h0);
    lo = ((uint32_t)__bfloat16_as_ushort(l1) << 16) | __bfloat16_as_ushort(l0);
}
__device__ __forceinline__ void split1(float v, __nv_bfloat16& h, __nv_bfloat16& l) {
    h = __float2bfloat16(v);
    l = __float2bfloat16(v - __bfloat162float(h));
}
__device__ __forceinline__ float bfu(unsigned short u) {
    __nv_bfloat16_raw r; r.x = u;
    return __bfloat162float(__nv_bfloat16(r));
}

// ---------------- scratch ---------------------------------------------------
__device__ float g_h0 [HW * HD];
__device__ float g_h1 [HW * HD];
__device__ float g_t  [HW];
__device__ float g_o  [BATCH * HW * INNER];
// weight images, 32KB packages (hi 16K + lo 16K), index (chunk*2 + nhalf):
//  [0,1]=W0'(tooW@modW0)  [2,3]=W1'  [4..7]=hvW0
//  [8]=qW(K=64)  [9]=bwW0  [10]=bwW1  [11..14]=toqW(256x128, nhalf 0 only)
__device__ __align__(128) uint8_t g_WB[15 * 2 * 32768];
__device__ float g_b0p[256];
__device__ float g_b1p[256];
// attention images
__device__ __align__(128) uint8_t g_qb[2 * 128 * 32768];
__device__ __align__(128) uint8_t g_kb[8 * 65536];
__device__ __align__(128) uint8_t g_vb[8 * 65536];

// ============================================================================
// K0: fold tooW@modW{0,1}; prep all split-bf16 swizzled weight images.
// ============================================================================
__global__ void k0_prepw(const float* __restrict__ tooW,
                         const float* __restrict__ modW0,
                         const float* __restrict__ modW1,
                         const float* __restrict__ hvW0,
                         const float* __restrict__ toob,
                         const float* __restrict__ modb0,
                         const float* __restrict__ modb1,
                         const float* __restrict__ qW,
                         const float* __restrict__ bwW0,
                         const float* __restrict__ bwW1,
                         const float* __restrict__ toqW)
{
    int m = blockIdx.y;           // 0..6
    int k = blockIdx.x;
    int n = threadIdx.x;
    float v;
    int chunk, nh, nrow;
    if (m < 2) {
        if (k >= 128) return;
        const float* modW = (m == 0) ? modW0 : modW1;
        float s = 0.f;
        for (int j = 0; j < 256; j++)
            s = fmaf(tooW[k * 256 + j], modW[j * 256 + n], s);
        v = s;
        chunk = m * 2 + (k >> 6);
        nh = n >> 7; nrow = n & 127;
        if (k == 0) {
            float bb = 0.f;
            for (int j = 0; j < 256; j++)
                bb = fmaf(toob[j], modW[j * 256 + n], bb);
            if (m == 0) g_b0p[n] = bb + modb0[n];
            else        g_b1p[n] = bb + modb1[n];
        }
    } else if (m == 2) {
        v = hvW0[k * 256 + n];
        chunk = 4 + (k >> 6); nh = n >> 7; nrow = n & 127;
    } else if (m == 3) {
        if (k >= 64) return;
        v = qW[k * 256 + n];
        chunk = 8; nh = n >> 7; nrow = n & 127;
    } else if (m == 4) {
        if (k >= 64) return;
        v = bwW0[k * 256 + n];
        chunk = 9; nh = n >> 7; nrow = n & 127;
    } else if (m == 5) {
        if (k >= 64) return;
        v = bwW1[k * 256 + n];
        chunk = 10; nh = n >> 7; nrow = n & 127;
    } else {
        if (n >= 128) return;
        v = toqW[k * 128 + n];
        chunk = 11 + (k >> 6); nh = 0; nrow = n;
    }
    __nv_bfloat16 h, l;
    split1(v, h, l);
    uint8_t* img = g_WB + ((size_t)chunk * 2 + nh) * 32768;
    int sw = swz(nrow * 128 + (k & 63) * 2);
    *(__nv_bfloat16*)(img + sw)         = h;
    *(__nv_bfloat16*)(img + 16384 + sw) = l;
}

// ============================================================================
// shared GEMM step (single accumulator, 8-warp layout) — used by k1.
// ============================================================================
__device__ __forceinline__ void run_gemm(char* smem, uint32_t sb, int Aoff, int loA,
                                         int mstart, int nch, int pass,
                                         int bufOff,
                                         int m0w, int n0p, int tid, int l,
                                         float* acc)
{
    {
        const uint8_t* src = g_WB + ((size_t)mstart * 2 + pass) * 32768;
        char* dst = smem + bufOff;
#pragma unroll
        for (int it = 0; it < 8; it++) {
            int i = (it * 256 + tid) * 16;
            cpa16(dst + i, src + i);
        }
        CPA_COMMIT();
    }
    for (int c = 0; c < nch; c++) {
        if (c + 1 < nch) {
            const uint8_t* src = g_WB + ((size_t)(mstart + c + 1) * 2 + pass) * 32768;
            char* dst = smem + bufOff + ((c + 1) & 1) * 32768;
#pragma unroll
            for (int it = 0; it < 8; it++) {
                int i = (it * 256 + tid) * 16;
                cpa16(dst + i, src + i);
            }
            CPA_COMMIT();
            CPA_WAIT1();
        } else {
            CPA_WAIT0();
        }
        __syncthreads();

        const uint32_t bB   = sb + bufOff + (c & 1) * 32768;
        const uint32_t bAhi = sb + Aoff + c * 8192;
        const uint32_t bAlo = bAhi + loA;

#pragma unroll
        for (int t4 = 0; t4 < 4; t4++) {
            uint32_t ahi[2][4], alo[2][4];
            const int arow = l & 15;
            const int akb  = t4 * 32 + (l >> 4) * 16;
#pragma unroll
            for (int mt = 0; mt < 2; mt++) {
                int ab = (m0w + mt * 16 + arow) * 128 + akb;
                int sw = swz(ab);
                ldsm4(ahi[mt], bAhi + sw);
                ldsm4(alo[mt], bAlo + sw);
            }
#pragma unroll
            for (int nt = 0; nt < 4; nt++) {
                const int nrow = n0p + nt * 8 + (l & 7);
                int bb = nrow * 128 + t4 * 32 + ((l >> 3) & 1) * 16;
                int sw = swz(bb);
                uint32_t bhi[2], blo[2];
                ldsm2(bhi, bB + sw);
                ldsm2(blo, bB + 16384 + sw);
                float* a0 = acc + (0 * 4 + nt) * 4;
                float* a1 = acc + (1 * 4 + nt) * 4;
                mma16816(a0, ahi[0], bhi);
                mma16816(a1, ahi[1], bhi);
                mma16816(a0, ahi[0], blo);
                mma16816(a1, ahi[1], blo);
                mma16816(a0, alo[0], bhi);
                mma16816(a1, alo[1], bhi);
            }
        }
        __syncthreads();
    }
}

// ============================================================================
// K1 mma: grid features on tensor cores (unchanged from R14).
// ============================================================================
#define SM1_FOUR  0
#define SM1_XQ    49152
#define SM1_B     114688
#define SM1_TOTAL 180224

__global__ void __launch_bounds__(256) k1_mma(
    const float* __restrict__ coords,
    const float* __restrict__ Bq,
    const float* __restrict__ Bl0,
    const float* __restrict__ Bl1,
    const float* __restrict__ qb,
    const float* __restrict__ bwb0,
    const float* __restrict__ bwb1)
{
    extern __shared__ uint8_t smemu[];
    char* smem = (char*)smemu;
    const uint32_t sb = smem_to_u32(smem);
    const int tid  = threadIdx.x;
    const int w    = tid >> 5;
    const int l    = tid & 31;
    const int m0w  = 32 * (w & 1);
    const int n0p  = 32 * (w >> 1);
    const int base = blockIdx.x * 64;

    for (int it = tid; it < 3 * 64 * 32; it += 256) {
        int mat = it >> 11;
        int rem = it & 2047;
        int r   = rem >> 5;
        int f   = rem & 31;
        float x = coords[(base + r) * 2 + 0];
        float y = coords[(base + r) * 2 + 1];
        const float* Bm = (mat == 0) ? Bq : (mat == 1 ? Bl0 : Bl1);
        float proj = TWO_PI * (x * Bm[f * 2] + y * Bm[f * 2 + 1]);
        float s, c;
        sincosf(proj, &s, &c);
        uint8_t* img = (uint8_t*)smem + SM1_FOUR + mat * 16384;
        __nv_bfloat16 hb, lb;
        split1(c, hb, lb);
        int sw = swz(r * 128 + f * 2);
        *(__nv_bfloat16*)(img + sw)        = hb;
        *(__nv_bfloat16*)(img + 8192 + sw) = lb;
        split1(s, hb, lb);
        sw = swz(r * 128 + (f + 32) * 2);
        *(__nv_bfloat16*)(img + sw)        = hb;
        *(__nv_bfloat16*)(img + 8192 + sw) = lb;
    }
    if (tid < 64) {
        float x = coords[(base + tid) * 2 + 0];
        float y = coords[(base + tid) * 2 + 1];
        int row = (int)(x * 16.0f); row = min(max(row, 0), 15);
        int col = (int)(y * 16.0f); col = min(max(col, 0), 15);
        g_t[base + tid] = (float)(row * 16 + col) * (1.0f / 256.0f);
    }
    __syncthreads();

    float acc[32];

#pragma unroll 1
    for (int pass = 0; pass < 2; pass++) {
#pragma unroll
        for (int i = 0; i < 32; i++) acc[i] = 0.f;
        run_gemm(smem, sb, SM1_FOUR, 8192, 8, 1, pass, SM1_B, m0w, n0p, tid, l, acc);
#pragma unroll
        for (int mt = 0; mt < 2; mt++)
#pragma unroll
        for (int nt = 0; nt < 4; nt++) {
            float* a = acc + (mt * 4 + nt) * 4;
            int c0 = pass * 128 + n0p + nt * 8 + (l & 3) * 2;
            int rA = m0w + mt * 16 + (l >> 2);
            float b0 = qb[c0], b1 = qb[c0 + 1];
            int kc = c0 >> 6;
            int bby = (c0 & 63) * 2;
#pragma unroll
            for (int half = 0; half < 2; half++) {
                int r = rA + half * 8;
                float v0 = fmaxf(a[half * 2 + 0] + b0, 0.f);
                float v1 = fmaxf(a[half * 2 + 1] + b1, 0.f);
                uint32_t hi, lo;
                split2(v0, v1, hi, lo);
                int sw = swz(r * 128 + bby);
                *(uint32_t*)(smem + SM1_XQ + kc * 8192 + sw)         = hi;
                *(uint32_t*)(smem + SM1_XQ + 32768 + kc * 8192 + sw) = lo;
            }
        }
    }
    __syncthreads();

    {
#pragma unroll
        for (int i = 0; i < 32; i++) acc[i] = 0.f;
        run_gemm(smem, sb, SM1_XQ, 32768, 11, 4, 0, SM1_B, m0w, n0p, tid, l, acc);
        const int tile = base >> 7;
        const int rb   = base & 127;
#pragma unroll
        for (int mt = 0; mt < 2; mt++)
#pragma unroll
        for (int nt = 0; nt < 4; nt++) {
            float* a = acc + (mt * 4 + nt) * 4;
            int c0 = n0p + nt * 8 + (l & 3) * 2;
            int h = c0 >> 6, d = c0 & 63;
            uint8_t* img = g_qb + (size_t)(h * 128 + tile) * 32768;
            int rA = m0w + mt * 16 + (l >> 2);
#pragma unroll
            for (int half = 0; half < 2; half++) {
                int rr = rb + rA + half * 8;
                float v0 = a[half * 2 + 0] * 0.125f;
                float v1 = a[half * 2 + 1] * 0.125f;
                uint32_t hi, lo;
                split2(v0, v1, hi, lo);
                int sw = swz(rr * 128 + d * 2);
                *(uint32_t*)(img + sw)         = hi;
                *(uint32_t*)(img + 16384 + sw) = lo;
            }
        }
    }

#pragma unroll 1
    for (int mat = 0; mat < 2; mat++) {
        const float* bw = mat ? bwb1 : bwb0;
        float* gh = mat ? g_h1 : g_h0;
#pragma unroll 1
        for (int pass = 0; pass < 2; pass++) {
#pragma unroll
            for (int i = 0; i < 32; i++) acc[i] = 0.f;
            run_gemm(smem, sb, SM1_FOUR + 16384 + mat * 16384, 8192, 9 + mat, 1, pass,
                     SM1_B, m0w, n0p, tid, l, acc);
#pragma unroll
            for (int mt = 0; mt < 2; mt++)
#pragma unroll
            for (int nt = 0; nt < 4; nt++) {
                float* a = acc + (mt * 4 + nt) * 4;
                int c0 = pass * 128 + n0p + nt * 8 + (l & 3) * 2;
                int rA = m0w + mt * 16 + (l >> 2);
                float b0 = bw[c0], b1 = bw[c0 + 1];
#pragma unroll
                for (int half = 0; half < 2; half++) {
                    int r = rA + half * 8;
                    float2 v;
                    v.x = fmaxf(a[half * 2 + 0] + b0, 0.f);
                    v.y = fmaxf(a[half * 2 + 1] + b1, 0.f);
                    *(float2*)&gh[(size_t)(base + r) * 256 + c0] = v;
                }
            }
        }
    }
}

// ============================================================================
// K2: kv = tokens @ tokvW -> split-bf16 swizzled k / v^T images (unchanged).
// ============================================================================
__global__ void k2_kv(const float* __restrict__ tokens,
                      const float* __restrict__ tokvW)
{
    __shared__ float tok[16][256];
    const int tile = blockIdx.x;
    const int b    = blockIdx.y;
    const int tid  = threadIdx.x;

    const float* tb = tokens + (b * MTOK + tile * 16) * 256;
    for (int i = tid; i < 16 * 256; i += 256) tok[i >> 8][i & 255] = tb[i];
    __syncthreads();

    const int j = tid;
    float acc[16];
#pragma unroll
    for (int r = 0; r < 16; r++) acc[r] = 0.f;
    for (int k = 0; k < 256; k++) {
        float w = tokvW[k * 256 + j];
#pragma unroll
        for (int r = 0; r < 16; r++) acc[r] = fmaf(tok[r][k], w, acc[r]);
    }
#pragma unroll
    for (int r = 0; r < 16; r++) {
        int m = tile * 16 + r;
        float v = acc[r];
        __nv_bfloat16 hb, lb;
        split1(v, hb, lb);
        if (j < 128) {
            int h = j >> 6, d = j & 63;
            uint8_t* img = g_kb + (size_t)(b * 2 + h) * 65536;
            int sw = swz(m * 128 + d * 2);
            *(__nv_bfloat16*)(img + sw)         = hb;
            *(__nv_bfloat16*)(img + 32768 + sw) = lb;
        } else {
            int h = (j - 128) >> 6, d = (j - 128) & 63;
            uint8_t* img = g_vb + (size_t)(b * 2 + h) * 65536;
            int off = (m >> 6) * 8192 + swz(d * 128 + (m & 63) * 2);
            *(__nv_bfloat16*)(img + off)         = hb;
            *(__nv_bfloat16*)(img + 32768 + off) = lb;
        }
    }
}

// ============================================================================
// K3 flash-mma attention (unchanged from R13).
// ============================================================================
__global__ void __launch_bounds__(256) k3_fa()
{
    extern __shared__ uint8_t smem[];
    const uint32_t sb = smem_to_u32(smem);
    const int tid = threadIdx.x;
    const int w   = tid >> 5;
    const int l   = tid & 31;
    const int bx  = blockIdx.x;
    const int h   = blockIdx.y;
    const int b   = blockIdx.z;

    {
        const uint8_t* qsrc = g_qb + (size_t)(h * 128 + bx) * 32768;
        const uint8_t* ksrc = g_kb + (size_t)(b * 2 + h) * 65536;
        const uint8_t* vsrc = g_vb + (size_t)(b * 2 + h) * 65536;
        for (int i = tid; i < 2048; i += 256) cpa16(smem + i * 16, qsrc + i * 16);
        for (int i = tid; i < 4096; i += 256) cpa16(smem + 32768 + i * 16, ksrc + i * 16);
        for (int i = tid; i < 4096; i += 256) cpa16(smem + 98304 + i * 16, vsrc + i * 16);
        CPA_COMMIT();
        CPA_WAIT0();
        __syncthreads();
    }
    const uint32_t sQh = sb,          sQl = sb + 16384;
    const uint32_t sKh = sb + 32768,  sKl = sb + 65536;
    const uint32_t sVh = sb + 98304,  sVl = sb + 131072;

    const int r0 = bx * 128 + w * 16 + (l >> 2);
    const float tt0 = g_t[r0];
    const float tt1 = g_t[r0 + 8];

    float O[32];
#pragma unroll
    for (int i = 0; i < 32; i++) O[i] = 0.f;
    float Mx0 = -1e30f, Mx1 = -1e30f, S0 = 0.f, S1 = 0.f;

    const int aQrow = (w * 16 + (l & 15)) * 128 + (l >> 4) * 16;

#pragma unroll 1
    for (int t = 0; t < 4; t++) {
        float Sa[32];
#pragma unroll
        for (int i = 0; i < 32; i++) Sa[i] = 0.f;

#pragma unroll
        for (int kk = 0; kk < 4; kk++) {
            int asw = swz(aQrow + kk * 32);
            uint32_t ahi[4], alo[4];
            ldsm4(ahi, sQh + asw);
            ldsm4(alo, sQl + asw);
#pragma unroll
            for (int nt = 0; nt < 8; nt++) {
                int bsw = swz((t * 64 + nt * 8 + (l & 7)) * 128 + kk * 32 + ((l >> 3) & 1) * 16);
                uint32_t bhi[2], blo[2];
                ldsm2(bhi, sKh + bsw);
                ldsm2(blo, sKl + bsw);
                mma16816(&Sa[nt * 4], ahi, bhi);
                mma16816(&Sa[nt * 4], ahi, blo);
                mma16816(&Sa[nt * 4], alo, bhi);
            }
        }

        float tm0 = -1e30f, tm1 = -1e30f;
#pragma unroll
        for (int nt = 0; nt < 8; nt++) {
            float* a = &Sa[nt * 4];
            float c0 = (float)(t * 64 + nt * 8 + (l & 3) * 2);
            float p0 = (c0 + 0.5f) * (1.0f / 256.0f);
            float p1 = (c0 + 1.5f) * (1.0f / 256.0f);
            float d00 = tt0 - p0, d01 = tt0 - p1;
            float d10 = tt1 - p0, d11 = tt1 - p1;
            a[0] -= 10.f * d00 * d00;
            a[1] -= 10.f * d01 * d01;
            a[2] -= 10.f * d10 * d10;
            a[3] -= 10.f * d11 * d11;
            tm0 = fmaxf(tm0, fmaxf(a[0], a[1]));
            tm1 = fmaxf(tm1, fmaxf(a[2], a[3]));
        }
        tm0 = fmaxf(tm0, __shfl_xor_sync(0xffffffffu, tm0, 1));
        tm0 = fmaxf(tm0, __shfl_xor_sync(0xffffffffu, tm0, 2));
        tm1 = fmaxf(tm1, __shfl_xor_sync(0xffffffffu, tm1, 1));
        tm1 = fmaxf(tm1, __shfl_xor_sync(0xffffffffu, tm1, 2));
        float nM0 = fmaxf(Mx0, tm0), nM1 = fmaxf(Mx1, tm1);
        float cr0 = __expf(Mx0 - nM0), cr1 = __expf(Mx1 - nM1);
        Mx0 = nM0; Mx1 = nM1;
        S0 *= cr0; S1 *= cr1;
#pragma unroll
        for (int nt = 0; nt < 8; nt++) {
            O[nt * 4 + 0] *= cr0; O[nt * 4 + 1] *= cr0;
            O[nt * 4 + 2] *= cr1; O[nt * 4 + 3] *= cr1;
        }
#pragma unroll
        for (int nt = 0; nt < 8; nt++) {
            float* a = &Sa[nt * 4];
            a[0] = __expf(a[0] - Mx0);
            a[1] = __expf(a[1] - Mx0);
            a[2] = __expf(a[2] - Mx1);
            a[3] = __expf(a[3] - Mx1);
            S0 += a[0] + a[1];
            S1 += a[2] + a[3];
        }

#pragma unroll
        for (int kk = 0; kk < 4; kk++) {
            uint32_t phi[4], plo[4];
            float* pA = &Sa[(2 * kk) * 4];
            float* pB = &Sa[(2 * kk + 1) * 4];
            split2(pA[0], pA[1], phi[0], plo[0]);
            split2(pA[2], pA[3], phi[1], plo[1]);
            split2(pB[0], pB[1], phi[2], plo[2]);
            split2(pB[2], pB[3], phi[3], plo[3]);
#pragma unroll
            for (int nt = 0; nt < 8; nt++) {
                int vsw = t * 8192 + swz((nt * 8 + (l & 7)) * 128 + kk * 32 + ((l >> 3) & 1) * 16);
                uint32_t vhi[2], vlo[2];
                ldsm2(vhi, sVh + vsw);
                ldsm2(vlo, sVl + vsw);
                mma16816(&O[nt * 4], phi, vhi);
                mma16816(&O[nt * 4], phi, vlo);
                mma16816(&O[nt * 4], plo, vhi);
            }
        }
    }

    S0 += __shfl_xor_sync(0xffffffffu, S0, 1);
    S0 += __shfl_xor_sync(0xffffffffu, S0, 2);
    S1 += __shfl_xor_sync(0xffffffffu, S1, 1);
    S1 += __shfl_xor_sync(0xffffffffu, S1, 2);
    float inv0 = 1.0f / S0, inv1 = 1.0f / S1;
#pragma unroll
    for (int nt = 0; nt < 8; nt++) {
        int col = h * 64 + nt * 8 + (l & 3) * 2;
        float2 o0, o1;
        o0.x = O[nt * 4 + 0] * inv0; o0.y = O[nt * 4 + 1] * inv0;
        o1.x = O[nt * 4 + 2] * inv1; o1.y = O[nt * 4 + 3] * inv1;
        *(float2*)&g_o[((size_t)b * HW + r0) * 128 + col]       = o0;
        *(float2*)&g_o[((size_t)b * HW + r0 + 8) * 128 + col]   = o1;
    }
}

// ============================================================================
// K5 v4: 32-row tiles, 128 threads, 2 CTAs/SM. Fused A+B with sequential
// W0'/W1' chunk loads into a single 32K B buffer; stage C single-buffered.
// ============================================================================
#define S5_O     0         // o image: hi 8K (2 chunks x 4K), lo at +8192
#define S5_X     16384     // x image: hi 16K (4 x 4K), lo at +16384
#define S5_B     49152     // single 32K weight buffer
#define S5_CONST 81920     // b0p|b1p|hvb|OW0|OW1 (2304 floats)
#define S5_PSM   91136     // 32 x 3 fp32
#define S5_TOTAL 91520

// load one 32KB weight package (index pkg) into S5_B. 128 threads.
__device__ __forceinline__ void k5_loadB(char* smem, int pkg, int tid)
{
    const uint8_t* src = g_WB + (size_t)pkg * 32768;
#pragma unroll
    for (int it = 0; it < 16; it++) {
        int i = (it * 128 + tid) * 16;
        cpa16(smem + S5_B + i, src + i);
    }
    CPA_COMMIT();
    CPA_WAIT0();
    __syncthreads();
}

// one 64-k chunk of mma: A at (bAhi,bAlo) 32 rows x 64 k, B = S5_B package.
__device__ __forceinline__ void k5_mma_chunk(uint32_t sb, uint32_t bAhi, uint32_t bAlo,
                                             int n0p, int l, float* acc)
{
    const uint32_t bB = sb + S5_B;
#pragma unroll
    for (int t4 = 0; t4 < 4; t4++) {
        uint32_t ahi[2][4], alo[2][4];
        const int arow = l & 15;
        const int akb  = t4 * 32 + (l >> 4) * 16;
#pragma unroll
        for (int mt = 0; mt < 2; mt++) {
            int sw = swz((mt * 16 + arow) * 128 + akb);
            ldsm4(ahi[mt], bAhi + sw);
            ldsm4(alo[mt], bAlo + sw);
        }
#pragma unroll
        for (int nt = 0; nt < 4; nt++) {
            const int nrow = n0p + nt * 8 + (l & 7);
            int sw = swz(nrow * 128 + t4 * 32 + ((l >> 3) & 1) * 16);
            uint32_t bhi[2], blo[2];
            ldsm2(bhi, bB + sw);
            ldsm2(blo, bB + 16384 + sw);
            float* q0 = acc + (0 * 4 + nt) * 4;
            float* q1 = acc + (1 * 4 + nt) * 4;
            mma16816(q0, ahi[0], bhi);
            mma16816(q1, ahi[1], bhi);
            mma16816(q0, ahi[0], blo);
            mma16816(q1, ahi[1], blo);
            mma16816(q0, alo[0], bhi);
            mma16816(q1, alo[1], bhi);
        }
    }
    __syncthreads();
}

__global__ void __launch_bounds__(128, 2) k5_mma(
    const float* __restrict__ hvb0,
    const float* __restrict__ outW0, const float* __restrict__ outb0,
    const float* __restrict__ outW1, const float* __restrict__ outb1,
    float* __restrict__ out)
{
    extern __shared__ char smemc[];
    char* smem = smemc;
    const uint32_t sb = smem_to_u32(smem);
    const int tid  = threadIdx.x;
    const int w    = tid >> 5;
    const int l    = tid & 31;
    const int n0p  = 32 * w;
    const int tile = blockIdx.x >> 2;
    const int bat  = blockIdx.x & 3;
    const int base = bat * HW + tile * 32;
    const int hb   = tile * 32;

    float* sC   = (float*)(smem + S5_CONST);
    float* sB0  = sC;
    float* sB1  = sC + 256;
    float* sHvb = sC + 512;
    float* sOW0 = sC + 768;
    float* sOW1 = sC + 1536;
    float* pSM  = (float*)(smem + S5_PSM);

    for (int i = tid; i < 256; i += 128) {
        sB0[i]  = g_b0p[i];
        sB1[i]  = g_b1p[i];
        sHvb[i] = hvb0[i];
    }
    for (int i = tid; i < 768; i += 128) {
        sOW0[i] = outW0[i];
        sOW1[i] = outW1[i];
    }
    for (int i = tid; i < 96; i += 128) pSM[i] = 0.f;

    // load o tile (32 x 128) -> split bf16 image
    for (int i = tid; i < 32 * 64; i += 128) {
        int r  = i >> 6;
        int kp = i & 63;
        int k  = kp * 2;
        float2 v = *(const float2*)&g_o[((size_t)(base + r)) * 128 + k];
        uint32_t hi, lo;
        split2(v.x, v.y, hi, lo);
        int kc = k >> 6;
        int sw = swz(r * 128 + (k & 63) * 2);
        *(uint32_t*)(smem + S5_O + kc * 4096 + sw)        = hi;
        *(uint32_t*)(smem + S5_O + 8192 + kc * 4096 + sw) = lo;
    }
    __syncthreads();

    float p[12];
#pragma unroll
    for (int i = 0; i < 12; i++) p[i] = 0.f;

    // ===== fused A+B: acc0 = o@W0', acc1 = o@W1' (sequential chunk loads) ===
#pragma unroll 1
    for (int pass = 0; pass < 2; pass++) {
        float a0[32], a1[32];
#pragma unroll
        for (int i = 0; i < 32; i++) { a0[i] = 0.f; a1[i] = 0.f; }

#pragma unroll 1
        for (int c = 0; c < 2; c++) {
            uint32_t bAhi = sb + S5_O + c * 4096;
            uint32_t bAlo = bAhi + 8192;
            k5_loadB(smem, (0 + c) * 2 + pass, tid);
            k5_mma_chunk(sb, bAhi, bAlo, n0p, l, a0);
            k5_loadB(smem, (2 + c) * 2 + pass, tid);
            k5_mma_chunk(sb, bAhi, bAlo, n0p, l, a1);
        }

        // fused epilogue: m0/m1 in regs; x -> S5_X; proj OW0 on m0
#pragma unroll
        for (int mt = 0; mt < 2; mt++)
#pragma unroll
        for (int nt = 0; nt < 4; nt++) {
            float* qa  = a0 + (mt * 4 + nt) * 4;
            float* qb2 = a1 + (mt * 4 + nt) * 4;
            int c0 = pass * 128 + n0p + nt * 8 + (l & 3) * 2;
            int rA = mt * 16 + (l >> 2);
            float b00 = sB0[c0], b01 = sB0[c0 + 1];
            float b10 = sB1[c0], b11 = sB1[c0 + 1];
            int kc = c0 >> 6;
            int bby = (c0 & 63) * 2;
#pragma unroll
            for (int half = 0; half < 2; half++) {
                int r = rA + half * 8;
                float2 h0 = *(const float2*)&g_h0[((size_t)(hb + r)) * 256 + c0];
                float2 h1 = *(const float2*)&g_h1[((size_t)(hb + r)) * 256 + c0];
                float m00 = fmaxf(h0.x + qa[half * 2 + 0] + b00, 0.f);
                float m01 = fmaxf(h0.y + qa[half * 2 + 1] + b01, 0.f);
                float m10 = fmaxf(h1.x + qb2[half * 2 + 0] + b10, 0.f);
                float m11 = fmaxf(h1.y + qb2[half * 2 + 1] + b11, 0.f);
                int slot = mt * 2 + half;
                p[slot * 3 + 0] = fmaf(m00, sOW0[c0 * 3 + 0], fmaf(m01, sOW0[c0 * 3 + 3], p[slot * 3 + 0]));
                p[slot * 3 + 1] = fmaf(m00, sOW0[c0 * 3 + 1], fmaf(m01, sOW0[c0 * 3 + 4], p[slot * 3 + 1]));
                p[slot * 3 + 2] = fmaf(m00, sOW0[c0 * 3 + 2], fmaf(m01, sOW0[c0 * 3 + 5], p[slot * 3 + 2]));
                float x0 = m00 + m10;
                float x1 = m01 + m11;
                uint32_t hi, lo;
                split2(x0, x1, hi, lo);
                int sw = swz(r * 128 + bby);
                *(uint32_t*)(smem + S5_X + kc * 4096 + sw)         = hi;
                *(uint32_t*)(smem + S5_X + 16384 + kc * 4096 + sw) = lo;
            }
        }
        __syncthreads();
    }

    // ===== stage C: hv1 = relu(x@hvW0 + b); proj OW1 ========================
#pragma unroll 1
    for (int pass = 0; pass < 2; pass++) {
        float acc[32];
#pragma unroll
        for (int i = 0; i < 32; i++) acc[i] = 0.f;
#pragma unroll 1
        for (int c = 0; c < 4; c++) {
            k5_loadB(smem, (4 + c) * 2 + pass, tid);
            k5_mma_chunk(sb, sb + S5_X + c * 4096, sb + S5_X + 16384 + c * 4096,
                         n0p, l, acc);
        }
#pragma unroll
        for (int mt = 0; mt < 2; mt++)
#pragma unroll
        for (int nt = 0; nt < 4; nt++) {
            float* a = acc + (mt * 4 + nt) * 4;
            int c0 = pass * 128 + n0p + nt * 8 + (l & 3) * 2;
            float b0 = sHvb[c0], b1 = sHvb[c0 + 1];
#pragma unroll
            for (int half = 0; half < 2; half++) {
                float v0 = fmaxf(a[half * 2 + 0] + b0, 0.f);
                float v1 = fmaxf(a[half * 2 + 1] + b1, 0.f);
                int slot = mt * 2 + half;
                p[slot * 3 + 0] = fmaf(v0, sOW1[c0 * 3 + 0], fmaf(v1, sOW1[c0 * 3 + 3], p[slot * 3 + 0]));
                p[slot * 3 + 1] = fmaf(v0, sOW1[c0 * 3 + 1], fmaf(v1, sOW1[c0 * 3 + 4], p[slot * 3 + 1]));
                p[slot * 3 + 2] = fmaf(v0, sOW1[c0 * 3 + 2], fmaf(v1, sOW1[c0 * 3 + 5], p[slot * 3 + 2]));
            }
        }
    }

    // ---- reduce projections ----
#pragma unroll
    for (int slot = 0; slot < 4; slot++) {
        int r = (slot >> 1) * 16 + (l >> 2) + (slot & 1) * 8;
#pragma unroll
        for (int j = 0; j < 3; j++) {
            float v = p[slot * 3 + j];
            v += __shfl_xor_sync(0xffffffffu, v, 1);
            v += __shfl_xor_sync(0xffffffffu, v, 2);
            if ((l & 3) == 0) atomicAdd(&pSM[r * 3 + j], v);
        }
    }
    __syncthreads();

    for (int i = tid; i < 96; i += 128) {
        int r = i / 3, j = i - r * 3;
        out[((size_t)(base + r)) * 3 + j] = pSM[i] + outb0[j] + outb1[j];
    }
}

// ============================================================================
extern "C" void kernel_launch(void* const* d_in, const int* in_sizes, int n_in,
                              void* d_out, int out_size)
{
    const float* coords = (const float*)d_in[0];
    const float* tokens = (const float*)d_in[1];
    const float* B_q    = (const float*)d_in[2];
    const float* B_l0   = (const float*)d_in[3];
    const float* B_l1   = (const float*)d_in[4];
    const float* qW     = (const float*)d_in[5];
    const float* qb     = (const float*)d_in[6];
    const float* toqW   = (const float*)d_in[7];
    const float* tokvW  = (const float*)d_in[8];
    const float* tooW   = (const float*)d_in[9];
    const float* toob   = (const float*)d_in[10];
    const float* bwW0   = (const float*)d_in[11];
    const float* bwb0   = (const float*)d_in[12];
    const float* bwW1   = (const float*)d_in[13];
    const float* bwb1   = (const float*)d_in[14];
    const float* modW0  = (const float*)d_in[15];
    const float* modb0  = (const float*)d_in[16];
    const float* modW1  = (const float*)d_in[17];
    const float* modb1  = (const float*)d_in[18];
    const float* hvW0   = (const float*)d_in[19];
    const float* hvb0   = (const float*)d_in[20];
    const float* outW0  = (const float*)d_in[21];
    const float* outb0  = (const float*)d_in[22];
    const float* outW1  = (const float*)d_in[23];
    const float* outb1  = (const float*)d_in[24];
    float* out = (float*)d_out;

    cudaFuncSetAttribute(k1_mma, cudaFuncAttributeMaxDynamicSharedMemorySize, SM1_TOTAL);
    cudaFuncSetAttribute(k3_fa,  cudaFuncAttributeMaxDynamicSharedMemorySize, 163840);
    cudaFuncSetAttribute(k5_mma, cudaFuncAttributeMaxDynamicSharedMemorySize, S5_TOTAL);

    k0_prepw<<<dim3(256, 7), 256>>>(tooW, modW0, modW1, hvW0, toob, modb0, modb1,
                                    qW, bwW0, bwW1, toqW);
    k1_mma<<<HW / 64, 256, SM1_TOTAL>>>(coords, B_q, B_l0, B_l1, qb, bwb0, bwb1);
    k2_kv<<<dim3(MTOK / 16, BATCH), 256>>>(tokens, tokvW);
    k3_fa<<<dim3(HW / 128, 2, BATCH), 256, 163840>>>();
    k5_mma<<<(BATCH * HW) / 32, 128, S5_TOTAL>>>(hvb0, outW0, outb0, outW1, outb1,
                                                 out);
}